// round 7
// baseline (speedup 1.0000x reference)
#include <cuda_runtime.h>
#include <cuda_bf16.h>

// Problem constants (fixed by the reference: b=8, c=512, k=19, h=w=128)
#define B     8
#define C     512
#define K     19
#define KPAD  20          // padded k for pairing
#define KP    10          // k-pairs
#define HW    16384       // 128*128
#define SPLIT 64          // hw split for pooled reduction (== FNC)

// Fused mask+pool tiling: 256 threads, 256 positions/block
#define FT    256
#define FCH   256
#define FNC   (HW / FCH)  // 64

// K4 tiling: 128 threads, 2 positions/thread -> 256 pos/block, 64x8=512 blocks
#define T1     128
#define POS    2
#define CHUNK  (T1 * POS)
#define NCHUNK (HW / CHUNK)

typedef unsigned long long u64;

// ---- static scratch (no allocations allowed) ----
__device__ float g_partial[B * SPLIT * K * C];  // ~20 MB
__device__ float g_cf[B * K * C];               // class_feat
__device__ float g_filt[B * K * C];             // filters

// ---- packed f32x2 helpers (SASS FFMA2 path) ----
__device__ __forceinline__ u64 pack2(float x, float y) {
    u64 r; asm("mov.b64 %0, {%1, %2};" : "=l"(r) : "f"(x), "f"(y)); return r;
}
__device__ __forceinline__ void unpack2(u64 v, float& x, float& y) {
    asm("mov.b64 {%0, %1}, %2;" : "=f"(x), "=f"(y) : "l"(v));
}
__device__ __forceinline__ void ffma2(u64& d, u64 a, u64 b) {
    asm("fma.rn.f32x2 %0, %1, %2, %0;" : "+l"(d) : "l"(a), "l"(b));
}

__device__ __forceinline__ float sigf(float v) {
    return 1.0f / (1.0f + __expf(-v));
}

// ============================================================
// K1+K2 fused: mask = sigmoid(Wm.x+bm) computed in-block, pooled
// against x immediately; mask never touches global memory.
// grid (FNC, B), FT=256 threads.
//   pass 1: thread = 1 position, all 19 classes (paired FFMA2,
//           weights smem [c][20]); mask tile -> smem overlay.
//   pass 2: thread = 2 channels {t, t+256}, reduce 256 positions
//           against smem mask tile; write g_partial[b][chunk][k][c].
// Pass-2 x reads hit L2 (concurrent block working set ~75MB < 126MB).
// ============================================================
__global__ void __launch_bounds__(FT) k_mask_pool(const float* __restrict__ x,
                                                  const float* __restrict__ Wm,
                                                  const float* __restrict__ bm)
{
    // overlay: pass1 weights (C*KPAD = 10240 floats, 40 KB)
    //          pass2 mask tile (K*FCH = 4864 floats, 19 KB)
    __shared__ __align__(16) float sbuf[C * KPAD];
    __shared__ __align__(8)  float sb[KPAD];
    const int tid = threadIdx.x;
    const int b = blockIdx.y;
    const int chunk = blockIdx.x;
    const int pbase = chunk * FCH;

    // ---- load paired weights ----
    for (int i = tid; i < C * KPAD; i += FT) {
        int c = i / KPAD, k = i - c * KPAD;
        sbuf[i] = (k < K) ? Wm[k * C + c] : 0.0f;
    }
    if (tid < KPAD) sb[tid] = (tid < K) ? bm[tid] : 0.0f;
    __syncthreads();

    // ---- pass 1: mask for position p = pbase + tid ----
    u64 acc[KP];
    {
        const u64* bp = reinterpret_cast<const u64*>(sb);
#pragma unroll
        for (int kp = 0; kp < KP; kp++) acc[kp] = bp[kp];
    }

    const float* xp = x + (size_t)b * C * HW + pbase + tid;
#pragma unroll 4
    for (int c = 0; c < C; c++) {
        float v = xp[(size_t)c * HW];
        u64 d = pack2(v, v);
        const u64* wp = reinterpret_cast<const u64*>(sbuf + c * KPAD);
#pragma unroll
        for (int kp = 0; kp < KP; kp++)
            ffma2(acc[kp], d, wp[kp]);
    }

    float m[KPAD];
#pragma unroll
    for (int kp = 0; kp < KP; kp++) {
        float a0, a1;
        unpack2(acc[kp], a0, a1);
        m[2 * kp]     = sigf(a0);
        m[2 * kp + 1] = sigf(a1);
    }

    __syncthreads();   // weights fully consumed -> overlay mask tile
    float* smask = sbuf;
#pragma unroll
    for (int k = 0; k < K; k++)
        smask[k * FCH + tid] = m[k];
    __syncthreads();

    // ---- pass 2: pooled partials for channels {tid, tid+256} ----
    const int c0 = tid;
    const int c1 = tid + 256;

    u64 acca[K], accb[K];
#pragma unroll
    for (int k = 0; k < K; k++) { acca[k] = 0ull; accb[k] = 0ull; }

    const ulonglong2* xa = reinterpret_cast<const ulonglong2*>(
        x + ((size_t)b * C + c0) * HW + pbase);
    const ulonglong2* xb = reinterpret_cast<const ulonglong2*>(
        x + ((size_t)b * C + c1) * HW + pbase);
    const ulonglong2* msp = reinterpret_cast<const ulonglong2*>(smask);

#pragma unroll 2
    for (int p4 = 0; p4 < FCH / 4; p4++) {
        ulonglong2 va = xa[p4];
        ulonglong2 vb = xb[p4];
#pragma unroll
        for (int k = 0; k < K; k++) {
            ulonglong2 mm = msp[k * (FCH / 4) + p4];
            ffma2(acca[k], mm.x, va.x);
            ffma2(acca[k], mm.y, va.y);
            ffma2(accb[k], mm.x, vb.x);
            ffma2(accb[k], mm.y, vb.y);
        }
    }

    float* outp = g_partial + (((size_t)b * SPLIT + chunk) * K) * C;
#pragma unroll
    for (int k = 0; k < K; k++) {
        float lo, hi;
        unpack2(acca[k], lo, hi);
        outp[(size_t)k * C + c0] = lo + hi;
        unpack2(accb[k], lo, hi);
        outp[(size_t)k * C + c1] = lo + hi;
    }
}

// ============================================================
// K2b: reduce partials -> class_feat[b][k][c] / HW
// ============================================================
__global__ void __launch_bounds__(128) k_reduce()
{
    const int bk = blockIdx.x;
    const int b = bk / K;
    const int k = bk - b * K;
    const int c = threadIdx.x * 4;

    float4 sum = make_float4(0.f, 0.f, 0.f, 0.f);
#pragma unroll 4
    for (int s = 0; s < SPLIT; s++) {
        const float4 v = *reinterpret_cast<const float4*>(
            g_partial + (((size_t)b * SPLIT + s) * K + k) * C + c);
        sum.x += v.x; sum.y += v.y; sum.z += v.z; sum.w += v.w;
    }
    const float inv = 1.0f / (float)HW;
    sum.x *= inv; sum.y *= inv; sum.z *= inv; sum.w *= inv;
    *reinterpret_cast<float4*>(g_cf + ((size_t)b * K + k) * C + c) = sum;
}

// ============================================================
// K3: filters[b][k][o] = Wf[k][o][:].cf[b][k][:] + bf[k][o]
// grid (8 o-tiles, K) — block handles 64 outputs x all 8 batches.
// cf for all 8 batches in smem (16 KB). Thread = (o_local, batch-pair).
// Wf streamed once per o-tile as float4 -> ~20 MB DRAM for the stage.
// ============================================================
__global__ void __launch_bounds__(256) k_filters(const float* __restrict__ Wf,
                                                 const float* __restrict__ bf)
{
    __shared__ __align__(16) float cfs[B][C];    // 16 KB
    const int k = blockIdx.y;
    const int o0 = blockIdx.x * 64;
    const int tid = threadIdx.x;

    for (int i = tid; i < B * C; i += 256) {
        int b = i >> 9;
        int c = i & 511;
        cfs[b][c] = g_cf[((size_t)b * K + k) * C + c];
    }
    __syncthreads();

    const int o_local = tid & 63;
    const int bp = tid >> 6;
    const int b0 = bp;
    const int b1 = bp + 4;
    const int o = o0 + o_local;

    const float4* wrow = reinterpret_cast<const float4*>(
        Wf + ((size_t)k * C + o) * C);

    float s0 = 0.f, s1 = 0.f;
#pragma unroll 4
    for (int c4 = 0; c4 < C / 4; c4++) {
        float4 w = wrow[c4];
        const float4 f0 = *reinterpret_cast<const float4*>(&cfs[b0][c4 * 4]);
        const float4 f1 = *reinterpret_cast<const float4*>(&cfs[b1][c4 * 4]);
        s0 += w.x * f0.x + w.y * f0.y + w.z * f0.z + w.w * f0.w;
        s1 += w.x * f1.x + w.y * f1.y + w.z * f1.z + w.w * f1.w;
    }

    const float bias = bf[(size_t)k * C + o];
    g_filt[((size_t)b0 * K + k) * C + o] = s0 + bias;
    g_filt[((size_t)b1 * K + k) * C + o] = s1 + bias;
}

// ============================================================
// K4: pred[b][k][hw] = sum_c filters[b][k][c] * x[b][c][hw]
// Paired-k FFMA2; grid (NCHUNK, B), 128 threads, 2 pos/thread.
// ============================================================
__global__ void __launch_bounds__(T1) k_pred(const float* __restrict__ x,
                                             float* __restrict__ out)
{
    __shared__ __align__(16) float sW[C * KPAD];
    const int tid = threadIdx.x;
    const int b = blockIdx.y;

    const float* fb = g_filt + (size_t)b * K * C;
    for (int i = tid; i < C * KPAD; i += T1) {
        int c = i / KPAD, k = i - c * KPAD;
        sW[i] = (k < K) ? fb[(size_t)k * C + c] : 0.0f;
    }
    __syncthreads();

    const int p0 = blockIdx.x * CHUNK + tid * POS;

    u64 acc[POS][KP];
#pragma unroll
    for (int kp = 0; kp < KP; kp++) { acc[0][kp] = 0ull; acc[1][kp] = 0ull; }

    const float2* xp = reinterpret_cast<const float2*>(
        x + (size_t)b * C * HW + p0);
    const int cstride = HW / 2;

#pragma unroll 4
    for (int c = 0; c < C; c++) {
        float2 v = xp[(size_t)c * cstride];
        u64 d0 = pack2(v.x, v.x);
        u64 d1 = pack2(v.y, v.y);
        const u64* wp = reinterpret_cast<const u64*>(sW + c * KPAD);
#pragma unroll
        for (int kp = 0; kp < KP; kp++) {
            u64 w = wp[kp];
            ffma2(acc[0][kp], d0, w);
            ffma2(acc[1][kp], d1, w);
        }
    }

#pragma unroll
    for (int kp = 0; kp < KP; kp++) {
        float a0k0, a0k1, a1k0, a1k1;
        unpack2(acc[0][kp], a0k0, a0k1);
        unpack2(acc[1][kp], a1k0, a1k1);
        int k0 = 2 * kp, k1 = 2 * kp + 1;
        float2 r0; r0.x = a0k0; r0.y = a1k0;
        *reinterpret_cast<float2*>(out + ((size_t)b * K + k0) * HW + p0) = r0;
        if (k1 < K) {
            float2 r1; r1.x = a0k1; r1.y = a1k1;
            *reinterpret_cast<float2*>(out + ((size_t)b * K + k1) * HW + p0) = r1;
        }
    }
}

// ============================================================
// launch
// ============================================================
extern "C" void kernel_launch(void* const* d_in, const int* in_sizes, int n_in,
                              void* d_out, int out_size)
{
    const float* x  = (const float*)d_in[0];
    const float* Wm = (const float*)d_in[1];
    const float* bm = (const float*)d_in[2];
    const float* Wf = (const float*)d_in[3];
    const float* bf = (const float*)d_in[4];
    float* out = (float*)d_out;

    k_mask_pool<<<dim3(FNC, B), FT>>>(x, Wm, bm);
    k_reduce<<<B * K, 128>>>();
    k_filters<<<dim3(C / 64, K), 256>>>(Wf, bf);
    k_pred<<<dim3(NCHUNK, B), T1>>>(x, out);
}

// round 11
// speedup vs baseline: 1.1582x; 1.1582x over previous
#include <cuda_runtime.h>
#include <cuda_bf16.h>

// Problem constants (fixed by the reference: b=8, c=512, k=19, h=w=128)
#define B     8
#define C     512
#define K     19
#define KPAD  20          // padded k for pairing
#define KP    10          // k-pairs
#define HW    16384       // 128*128
#define SPLIT 64          // hw split for pooled reduction
#define PCH   (HW / SPLIT)

// K1/K4 tiling: 128 threads, 4 positions/thread -> 512 pos/block, 32x8=256 blocks
#define T1     128
#define POS    4
#define CHUNK  (T1 * POS)
#define NCHUNK (HW / CHUNK)

typedef unsigned long long u64;

// ---- static scratch (no allocations allowed) ----
__device__ float g_mask[B * K * HW];            // ~10 MB
__device__ float g_partial[B * SPLIT * K * C];  // ~20 MB
__device__ float g_cf[B * K * C];               // class_feat
__device__ float g_filt[B * K * C];             // filters

// ---- packed f32x2 helpers (SASS FFMA2 path) ----
__device__ __forceinline__ u64 pack2(float x, float y) {
    u64 r; asm("mov.b64 %0, {%1, %2};" : "=l"(r) : "f"(x), "f"(y)); return r;
}
__device__ __forceinline__ void unpack2(u64 v, float& x, float& y) {
    asm("mov.b64 {%0, %1}, %2;" : "=f"(x), "=f"(y) : "l"(v));
}
__device__ __forceinline__ void ffma2(u64& d, u64 a, u64 b) {
    asm("fma.rn.f32x2 %0, %1, %2, %0;" : "+l"(d) : "l"(a), "l"(b));
}

__device__ __forceinline__ float sigf(float v) {
    return 1.0f / (1.0f + __expf(-v));
}

// ============================================================
// K1: mask = sigmoid(Wm . x + bm)   [b,k,hw]
// grid (NCHUNK, B), T1=128 threads, POS=4 positions/thread.
// 40 independent FFMA2 chains/thread. launch_bounds(128,2):
// ~256-reg budget so the ~140-reg natural demand does NOT spill.
// ============================================================
__global__ void __launch_bounds__(T1, 2) k_mask(const float* __restrict__ x,
                                                const float* __restrict__ Wm,
                                                const float* __restrict__ bm)
{
    __shared__ __align__(16) float sW[C * KPAD];   // 40 KB
    __shared__ __align__(8)  float sb[KPAD];
    const int tid = threadIdx.x;
    const int b = blockIdx.y;

    for (int i = tid; i < C * KPAD; i += T1) {
        int c = i / KPAD, k = i - c * KPAD;
        sW[i] = (k < K) ? Wm[k * C + c] : 0.0f;
    }
    if (tid < KPAD) sb[tid] = (tid < K) ? bm[tid] : 0.0f;
    __syncthreads();

    const int p0 = blockIdx.x * CHUNK + tid * POS;

    u64 acc[POS][KP];
    {
        const u64* bp = reinterpret_cast<const u64*>(sb);
#pragma unroll
        for (int kp = 0; kp < KP; kp++) {
            u64 bv = bp[kp];
#pragma unroll
            for (int j = 0; j < POS; j++) acc[j][kp] = bv;
        }
    }

    const float4* xp = reinterpret_cast<const float4*>(
        x + (size_t)b * C * HW + p0);
    const int cstride = HW / 4;

#pragma unroll 2
    for (int c = 0; c < C; c++) {
        float4 v = xp[(size_t)c * cstride];
        u64 d0 = pack2(v.x, v.x);
        u64 d1 = pack2(v.y, v.y);
        u64 d2 = pack2(v.z, v.z);
        u64 d3 = pack2(v.w, v.w);
        const u64* wp = reinterpret_cast<const u64*>(sW + c * KPAD);
#pragma unroll
        for (int kp = 0; kp < KP; kp++) {
            u64 w = wp[kp];
            ffma2(acc[0][kp], d0, w);
            ffma2(acc[1][kp], d1, w);
            ffma2(acc[2][kp], d2, w);
            ffma2(acc[3][kp], d3, w);
        }
    }

#pragma unroll
    for (int kp = 0; kp < KP; kp++) {
        float a[POS][2];
#pragma unroll
        for (int j = 0; j < POS; j++) unpack2(acc[j][kp], a[j][0], a[j][1]);
        int k0 = 2 * kp, k1 = 2 * kp + 1;
        float4 m0;
        m0.x = sigf(a[0][0]); m0.y = sigf(a[1][0]);
        m0.z = sigf(a[2][0]); m0.w = sigf(a[3][0]);
        *reinterpret_cast<float4*>(g_mask + ((size_t)b * K + k0) * HW + p0) = m0;
        if (k1 < K) {
            float4 m1;
            m1.x = sigf(a[0][1]); m1.y = sigf(a[1][1]);
            m1.z = sigf(a[2][1]); m1.w = sigf(a[3][1]);
            *reinterpret_cast<float4*>(g_mask + ((size_t)b * K + k1) * HW + p0) = m1;
        }
    }
}

// ============================================================
// K2: partial pooled features (packed over positions).
// grid (SPLIT, B), 256 threads. Thread owns channels {t, t+256};
// 19 class accumulators per channel as f32x2 pairs.
// ============================================================
__global__ void __launch_bounds__(256) k_pool(const float* __restrict__ x)
{
    __shared__ __align__(16) float ms[K * PCH];   // 19 KB mask tile
    const int tid = threadIdx.x;
    const int s = blockIdx.x;
    const int b = blockIdx.y;
    const int pbase = s * PCH;

    for (int i = tid; i < K * PCH; i += 256) {
        int k = i / PCH;
        int p = i - k * PCH;
        ms[i] = g_mask[((size_t)b * K + k) * HW + pbase + p];
    }
    __syncthreads();

    const int c0 = tid;
    const int c1 = tid + 256;

    u64 acca[K], accb[K];
#pragma unroll
    for (int k = 0; k < K; k++) { acca[k] = 0ull; accb[k] = 0ull; }

    const ulonglong2* xa = reinterpret_cast<const ulonglong2*>(
        x + ((size_t)b * C + c0) * HW + pbase);
    const ulonglong2* xb = reinterpret_cast<const ulonglong2*>(
        x + ((size_t)b * C + c1) * HW + pbase);
    const ulonglong2* msp = reinterpret_cast<const ulonglong2*>(ms);

#pragma unroll 2
    for (int p4 = 0; p4 < PCH / 4; p4++) {
        ulonglong2 va = xa[p4];
        ulonglong2 vb = xb[p4];
#pragma unroll
        for (int k = 0; k < K; k++) {
            ulonglong2 mm = msp[k * (PCH / 4) + p4];
            ffma2(acca[k], mm.x, va.x);
            ffma2(acca[k], mm.y, va.y);
            ffma2(accb[k], mm.x, vb.x);
            ffma2(accb[k], mm.y, vb.y);
        }
    }

    float* outp = g_partial + (((size_t)b * SPLIT + s) * K) * C;
#pragma unroll
    for (int k = 0; k < K; k++) {
        float lo, hi;
        unpack2(acca[k], lo, hi);
        outp[(size_t)k * C + c0] = lo + hi;
        unpack2(accb[k], lo, hi);
        outp[(size_t)k * C + c1] = lo + hi;
    }
}

// ============================================================
// K2b: reduce partials -> class_feat[b][k][c] / HW
// ============================================================
__global__ void __launch_bounds__(128) k_reduce()
{
    const int bk = blockIdx.x;
    const int b = bk / K;
    const int k = bk - b * K;
    const int c = threadIdx.x * 4;

    float4 sum = make_float4(0.f, 0.f, 0.f, 0.f);
#pragma unroll 4
    for (int s = 0; s < SPLIT; s++) {
        const float4 v = *reinterpret_cast<const float4*>(
            g_partial + (((size_t)b * SPLIT + s) * K + k) * C + c);
        sum.x += v.x; sum.y += v.y; sum.z += v.z; sum.w += v.w;
    }
    const float inv = 1.0f / (float)HW;
    sum.x *= inv; sum.y *= inv; sum.z *= inv; sum.w *= inv;
    *reinterpret_cast<float4*>(g_cf + ((size_t)b * K + k) * C + c) = sum;
}

// ============================================================
// K3: filters[b][k][o] = Wf[k][o][:].cf[b][k][:] + bf[k][o]
// grid (8 o-tiles, K) — block handles 64 outputs x all 8 batches.
// cf for all 8 batches in smem (16 KB). Thread = (o_local, batch-pair).
// Wf streamed once per o-tile as float4 -> ~20 MB DRAM for the stage.
// ============================================================
__global__ void __launch_bounds__(256) k_filters(const float* __restrict__ Wf,
                                                 const float* __restrict__ bf)
{
    __shared__ __align__(16) float cfs[B][C];    // 16 KB
    const int k = blockIdx.y;
    const int o0 = blockIdx.x * 64;
    const int tid = threadIdx.x;

    for (int i = tid; i < B * C; i += 256) {
        int b = i >> 9;
        int c = i & 511;
        cfs[b][c] = g_cf[((size_t)b * K + k) * C + c];
    }
    __syncthreads();

    const int o_local = tid & 63;
    const int bp = tid >> 6;
    const int b0 = bp;
    const int b1 = bp + 4;
    const int o = o0 + o_local;

    const float4* wrow = reinterpret_cast<const float4*>(
        Wf + ((size_t)k * C + o) * C);

    float s0 = 0.f, s1 = 0.f;
#pragma unroll 4
    for (int c4 = 0; c4 < C / 4; c4++) {
        float4 w = wrow[c4];
        const float4 f0 = *reinterpret_cast<const float4*>(&cfs[b0][c4 * 4]);
        const float4 f1 = *reinterpret_cast<const float4*>(&cfs[b1][c4 * 4]);
        s0 += w.x * f0.x + w.y * f0.y + w.z * f0.z + w.w * f0.w;
        s1 += w.x * f1.x + w.y * f1.y + w.z * f1.z + w.w * f1.w;
    }

    const float bias = bf[(size_t)k * C + o];
    g_filt[((size_t)b0 * K + k) * C + o] = s0 + bias;
    g_filt[((size_t)b1 * K + k) * C + o] = s1 + bias;
}

// ============================================================
// K4: pred[b][k][hw] = sum_c filters[b][k][c] * x[b][c][hw]
// grid (NCHUNK, B), T1=128, POS=4. launch_bounds(128,2): no spills.
// ============================================================
__global__ void __launch_bounds__(T1, 2) k_pred(const float* __restrict__ x,
                                                float* __restrict__ out)
{
    __shared__ __align__(16) float sW[C * KPAD];
    const int tid = threadIdx.x;
    const int b = blockIdx.y;

    const float* fb = g_filt + (size_t)b * K * C;
    for (int i = tid; i < C * KPAD; i += T1) {
        int c = i / KPAD, k = i - c * KPAD;
        sW[i] = (k < K) ? fb[(size_t)k * C + c] : 0.0f;
    }
    __syncthreads();

    const int p0 = blockIdx.x * CHUNK + tid * POS;

    u64 acc[POS][KP];
#pragma unroll
    for (int kp = 0; kp < KP; kp++) {
#pragma unroll
        for (int j = 0; j < POS; j++) acc[j][kp] = 0ull;
    }

    const float4* xp = reinterpret_cast<const float4*>(
        x + (size_t)b * C * HW + p0);
    const int cstride = HW / 4;

#pragma unroll 2
    for (int c = 0; c < C; c++) {
        float4 v = xp[(size_t)c * cstride];
        u64 d0 = pack2(v.x, v.x);
        u64 d1 = pack2(v.y, v.y);
        u64 d2 = pack2(v.z, v.z);
        u64 d3 = pack2(v.w, v.w);
        const u64* wp = reinterpret_cast<const u64*>(sW + c * KPAD);
#pragma unroll
        for (int kp = 0; kp < KP; kp++) {
            u64 w = wp[kp];
            ffma2(acc[0][kp], d0, w);
            ffma2(acc[1][kp], d1, w);
            ffma2(acc[2][kp], d2, w);
            ffma2(acc[3][kp], d3, w);
        }
    }

#pragma unroll
    for (int kp = 0; kp < KP; kp++) {
        float a[POS][2];
#pragma unroll
        for (int j = 0; j < POS; j++) unpack2(acc[j][kp], a[j][0], a[j][1]);
        int k0 = 2 * kp, k1 = 2 * kp + 1;
        float4 r0;
        r0.x = a[0][0]; r0.y = a[1][0]; r0.z = a[2][0]; r0.w = a[3][0];
        *reinterpret_cast<float4*>(out + ((size_t)b * K + k0) * HW + p0) = r0;
        if (k1 < K) {
            float4 r1;
            r1.x = a[0][1]; r1.y = a[1][1]; r1.z = a[2][1]; r1.w = a[3][1];
            *reinterpret_cast<float4*>(out + ((size_t)b * K + k1) * HW + p0) = r1;
        }
    }
}

// ============================================================
// launch
// ============================================================
extern "C" void kernel_launch(void* const* d_in, const int* in_sizes, int n_in,
                              void* d_out, int out_size)
{
    const float* x  = (const float*)d_in[0];
    const float* Wm = (const float*)d_in[1];
    const float* bm = (const float*)d_in[2];
    const float* Wf = (const float*)d_in[3];
    const float* bf = (const float*)d_in[4];
    float* out = (float*)d_out;

    k_mask<<<dim3(NCHUNK, B), T1>>>(x, Wm, bm);
    k_pool<<<dim3(SPLIT, B), 256>>>(x);
    k_reduce<<<B * K, 128>>>();
    k_filters<<<dim3(C / 64, K), 256>>>(Wf, bf);
    k_pred<<<dim3(NCHUNK, B), T1>>>(x, out);
}